// round 2
// baseline (speedup 1.0000x reference)
#include <cuda_runtime.h>
#include <cuda_bf16.h>
#include <math.h>

// Problem constants
#define NIMG   32
#define HH     96
#define WW     96
#define LPIX   (HH*WW)              // 9216
#define MROWS  (NIMG*LPIX)          // 294912
#define CDIM   256
#define HID    256
#define NBINS  17
#define REGOUT (4*NBINS)            // 68
#define REGCH  64

// Scratch (device globals: allocation-guard safe)
__device__ float g_bufA[(size_t)MROWS * 256];
__device__ float g_bufB[(size_t)MROWS * 256];
__device__ float g_cls[MROWS];

// ---------------------------------------------------------------------------
// Tiled SGEMM: C[M, Nout] = act(A[M, K] * W[Nout, K]^T + bias)
// BM=128, BN=128, BK=16, 256 threads, 8x8 per-thread tile.
// ---------------------------------------------------------------------------
#define BM 128
#define BN 128
#define BK 16

__global__ void __launch_bounds__(256, 2)
sgemm_bias_act(const float* __restrict__ A,
               const float* __restrict__ W,
               const float* __restrict__ bias,
               float* __restrict__ C,
               int M, int Nout, int K, int relu)
{
    __shared__ __align__(16) float As[BK][BM];
    __shared__ __align__(16) float Bs[BK][BN];

    const int bm = blockIdx.y * BM;
    const int bn = blockIdx.x * BN;
    const int tid = threadIdx.x;
    const int ty = tid >> 4;        // 0..15
    const int tx = tid & 15;        // 0..15

    float acc[8][8];
#pragma unroll
    for (int i = 0; i < 8; i++)
#pragma unroll
        for (int j = 0; j < 8; j++) acc[i][j] = 0.f;

    for (int k0 = 0; k0 < K; k0 += BK) {
        // Load A tile (BM x BK) transposed into As[BK][BM]
#pragma unroll
        for (int it = 0; it < 2; it++) {
            int i = tid + it * 256;           // 0..511 float4 slots
            int r  = i >> 2;                  // row 0..127
            int c4 = (i & 3) << 2;            // 0,4,8,12
            float4 v = *(const float4*)&A[(size_t)(bm + r) * K + k0 + c4];
            As[c4 + 0][r] = v.x;
            As[c4 + 1][r] = v.y;
            As[c4 + 2][r] = v.z;
            As[c4 + 3][r] = v.w;
        }
        // Load W tile: Bs[k][n] = W[(bn+n)*K + k0+k]
#pragma unroll
        for (int it = 0; it < 2; it++) {
            int i = tid + it * 256;
            int n  = i >> 2;
            int c4 = (i & 3) << 2;
            float4 v = make_float4(0.f, 0.f, 0.f, 0.f);
            if (bn + n < Nout)
                v = *(const float4*)&W[(size_t)(bn + n) * K + k0 + c4];
            Bs[c4 + 0][n] = v.x;
            Bs[c4 + 1][n] = v.y;
            Bs[c4 + 2][n] = v.z;
            Bs[c4 + 3][n] = v.w;
        }
        __syncthreads();

#pragma unroll
        for (int k = 0; k < BK; k++) {
            float4 a0 = *(const float4*)&As[k][ty * 8];
            float4 a1 = *(const float4*)&As[k][ty * 8 + 4];
            float4 b0 = *(const float4*)&Bs[k][tx * 8];
            float4 b1 = *(const float4*)&Bs[k][tx * 8 + 4];
            float ra[8] = {a0.x, a0.y, a0.z, a0.w, a1.x, a1.y, a1.z, a1.w};
            float rb[8] = {b0.x, b0.y, b0.z, b0.w, b1.x, b1.y, b1.z, b1.w};
#pragma unroll
            for (int i = 0; i < 8; i++)
#pragma unroll
                for (int j = 0; j < 8; j++)
                    acc[i][j] = fmaf(ra[i], rb[j], acc[i][j]);
        }
        __syncthreads();
    }

    // Epilogue: bias + optional relu, float4 stores with N guard
    const int row0 = bm + ty * 8;
    const int col0 = bn + tx * 8;
#pragma unroll
    for (int i = 0; i < 8; i++) {
        float* crow = &C[(size_t)(row0 + i) * Nout];
#pragma unroll
        for (int jq = 0; jq < 2; jq++) {
            int c = col0 + jq * 4;
            if (c < Nout) {   // Nout is a multiple of 4 here (256 or 68)
                float4 v;
                v.x = acc[i][jq * 4 + 0] + bias[c + 0];
                v.y = acc[i][jq * 4 + 1] + bias[c + 1];
                v.z = acc[i][jq * 4 + 2] + bias[c + 2];
                v.w = acc[i][jq * 4 + 3] + bias[c + 3];
                if (relu) {
                    v.x = fmaxf(v.x, 0.f);
                    v.y = fmaxf(v.y, 0.f);
                    v.z = fmaxf(v.z, 0.f);
                    v.w = fmaxf(v.w, 0.f);
                }
                *(float4*)&crow[c] = v;
            }
        }
    }
}

// ---------------------------------------------------------------------------
// cls logit: out[r] = dot(H[r, 0:256], w[0:256]) + b[0]   (warp per row)
// 256 threads = 8 warps per block -> grid MUST be MROWS/8 blocks.
// ---------------------------------------------------------------------------
__global__ void __launch_bounds__(256)
dot256_kernel(const float* __restrict__ H, const float* __restrict__ w,
              const float* __restrict__ bptr, float* __restrict__ out, int M)
{
    int gwarp = (blockIdx.x * blockDim.x + threadIdx.x) >> 5;
    int lane = threadIdx.x & 31;
    if (gwarp >= M) return;
    const float* h = H + (size_t)gwarp * 256;
    float s = 0.f;
#pragma unroll
    for (int i = 0; i < 8; i++)
        s = fmaf(h[lane + 32 * i], __ldg(&w[lane + 32 * i]), s);
#pragma unroll
    for (int o = 16; o; o >>= 1) s += __shfl_xor_sync(0xffffffffu, s, o);
    if (lane == 0) out[gwarp] = s + __ldg(bptr);
}

// ---------------------------------------------------------------------------
// Head: per pixel — softmax-17 per side, top4+mean stats, quality MLP,
// sigmoid(cls)*quality, integral box.
// ---------------------------------------------------------------------------
__global__ void __launch_bounds__(128)
head_kernel(const float* __restrict__ reg,    // [M, 68]
            const float* __restrict__ clsl,   // [M]
            const float* __restrict__ qw1,    // [64, 20]
            const float* __restrict__ qb1,    // [64]
            const float* __restrict__ qw2,    // [1, 64]
            const float* __restrict__ qb2,    // [1]
            float* __restrict__ outCls,       // [M]
            float* __restrict__ outBox,       // [M, 4]
            int M)
{
    __shared__ float sw1[REGCH * 20];
    __shared__ float sb1[REGCH];
    __shared__ float sw2[REGCH];
    __shared__ float sb2;
    for (int i = threadIdx.x; i < REGCH * 20; i += blockDim.x) sw1[i] = qw1[i];
    for (int i = threadIdx.x; i < REGCH; i += blockDim.x) {
        sb1[i] = qb1[i];
        sw2[i] = qw2[i];
    }
    if (threadIdx.x == 0) sb2 = qb2[0];
    __syncthreads();

    int p = blockIdx.x * blockDim.x + threadIdx.x;
    if (p >= M) return;

    const float* rp = reg + (size_t)p * REGOUT;
    float stat[20];
    float box[4];

#pragma unroll
    for (int s = 0; s < 4; s++) {
        float v[NBINS];
        float mx = -1e30f;
#pragma unroll
        for (int i = 0; i < NBINS; i++) {
            v[i] = rp[s * NBINS + i];
            mx = fmaxf(mx, v[i]);
        }
        float sum = 0.f;
#pragma unroll
        for (int i = 0; i < NBINS; i++) {
            v[i] = expf(v[i] - mx);
            sum += v[i];
        }
        float inv = 1.f / sum;
        float integ = 0.f;
#pragma unroll
        for (int i = 0; i < NBINS; i++) {
            v[i] *= inv;
            integ += v[i] * (float)i;
        }
        box[s] = integ * (1.f / 16.f);
        float mean4 = 0.f;
        for (int k = 0; k < 4; k++) {
            float best = -1.f;
            int bi = 0;
#pragma unroll
            for (int i = 0; i < NBINS; i++) {
                if (v[i] > best) { best = v[i]; bi = i; }
            }
            stat[s * 5 + k] = best;
            mean4 += best;
            v[bi] = -2.f;
        }
        stat[s * 5 + 4] = mean4 * 0.25f;
    }

    // quality = sigmoid(qw2 . relu(qw1 . stat + qb1) + qb2)
    float q = sb2;
    for (int o = 0; o < REGCH; o++) {
        float h = sb1[o];
#pragma unroll
        for (int c = 0; c < 20; c++) h = fmaf(sw1[o * 20 + c], stat[c], h);
        h = fmaxf(h, 0.f);
        q = fmaf(sw2[o], h, q);
    }
    q = 1.f / (1.f + expf(-q));
    float cl = 1.f / (1.f + expf(-clsl[p]));

    outCls[p] = cl * q;
    float4 b4 = make_float4(box[0], box[1], box[2], box[3]);
    *(float4*)&outBox[(size_t)p * 4] = b4;
}

// ---------------------------------------------------------------------------
// Launcher
// ---------------------------------------------------------------------------
extern "C" void kernel_launch(void* const* d_in, const int* in_sizes, int n_in,
                              void* d_out, int out_size)
{
    const float* x   = (const float*)d_in[0];
    const float* cw1 = (const float*)d_in[1];
    const float* cb1 = (const float*)d_in[2];
    const float* cw2 = (const float*)d_in[3];
    const float* cb2 = (const float*)d_in[4];
    const float* cw3 = (const float*)d_in[5];
    const float* cb3 = (const float*)d_in[6];
    const float* rw1 = (const float*)d_in[7];
    const float* rb1 = (const float*)d_in[8];
    const float* rw2 = (const float*)d_in[9];
    const float* rb2 = (const float*)d_in[10];
    const float* rw3 = (const float*)d_in[11];
    const float* rb3 = (const float*)d_in[12];
    const float* qw1 = (const float*)d_in[13];
    const float* qb1 = (const float*)d_in[14];
    const float* qw2 = (const float*)d_in[15];
    const float* qb2 = (const float*)d_in[16];

    float* out = (float*)d_out;
    float* outCls = out;                              // M
    float* outBox = out + (size_t)MROWS;              // M*4
    float* outReg = out + (size_t)MROWS * 5;          // M*68

    float *bufA, *bufB, *clsbuf;
    cudaGetSymbolAddress((void**)&bufA, g_bufA);
    cudaGetSymbolAddress((void**)&bufB, g_bufB);
    cudaGetSymbolAddress((void**)&clsbuf, g_cls);

    dim3 grid256(2, MROWS / BM);   // Nout=256 -> 2 column blocks
    dim3 grid68(1, MROWS / BM);    // Nout=68  -> 1 column block
    dim3 blk(256);

    // Classification branch
    sgemm_bias_act<<<grid256, blk>>>(x,    cw1, cb1, bufA, MROWS, 256, 256, 1);
    sgemm_bias_act<<<grid256, blk>>>(bufA, cw2, cb2, bufB, MROWS, 256, 256, 1);
    dot256_kernel<<<MROWS / 8, 256>>>(bufB, cw3, cb3, clsbuf, MROWS);

    // Regression branch
    sgemm_bias_act<<<grid256, blk>>>(x,    rw1, rb1, bufA, MROWS, 256, 256, 1);
    sgemm_bias_act<<<grid256, blk>>>(bufA, rw2, rb2, bufB, MROWS, 256, 256, 1);
    sgemm_bias_act<<<grid68,  blk>>>(bufB, rw3, rb3, outReg, MROWS, REGOUT, 256, 0);

    // Fused head
    head_kernel<<<(MROWS + 127) / 128, 128>>>(outReg, clsbuf, qw1, qb1, qw2, qb2,
                                              outCls, outBox, MROWS);
}

// round 4
// speedup vs baseline: 3.2116x; 3.2116x over previous
#include <cuda_runtime.h>
#include <cuda_bf16.h>
#include <math.h>
#include <stdint.h>

// Problem constants
#define NIMG   32
#define HH     96
#define WW     96
#define LPIX   (HH*WW)              // 9216
#define MROWS  (NIMG*LPIX)          // 294912
#define NBINS  17
#define REGOUT (4*NBINS)            // 68
#define REGCH  64

// ---------------------------------------------------------------------------
// Scratch device globals (allocation-guard safe)
// ---------------------------------------------------------------------------
__device__ __align__(16) float g_xa[(size_t)MROWS * 256];    // tf32-rounded x
__device__ __align__(16) float g_bufA[(size_t)MROWS * 256];
__device__ __align__(16) float g_bufB[(size_t)MROWS * 256];
__device__ float g_cls[MROWS];
// rounded weights: cw1, cw2, rw1, rw2 (256x256 each) + rw3 (68x256)
__device__ __align__(16) float g_wr[(size_t)(4 * 256 + 68) * 256];

// ---------------------------------------------------------------------------
// helpers
// ---------------------------------------------------------------------------
__device__ __forceinline__ uint32_t smem_u32(const void* p) {
    uint32_t a;
    asm("{ .reg .u64 t; cvta.to.shared.u64 t, %1; cvt.u32.u64 %0, t; }" : "=r"(a) : "l"(p));
    return a;
}
__device__ __forceinline__ float tf32r(float x) {
    uint32_t u;
    asm("cvt.rna.tf32.f32 %0, %1;" : "=r"(u) : "f"(x));
    return __uint_as_float(u);
}
#define CP16(dst, gsrc, nbytes) \
    asm volatile("cp.async.cg.shared.global [%0], [%1], 16, %2;" \
                 :: "r"(dst), "l"(gsrc), "r"(nbytes))
#define CP_COMMIT() asm volatile("cp.async.commit_group;" ::: "memory")
#define CP_WAIT(n)  asm volatile("cp.async.wait_group %0;" :: "n"(n) : "memory")

#define MMA8(c, a, b)                                                        \
    asm volatile("mma.sync.aligned.m16n8k8.row.col.f32.tf32.tf32.f32 "       \
        "{%0,%1,%2,%3}, {%4,%5,%6,%7}, {%8,%9}, {%0,%1,%2,%3};"              \
        : "+f"((c)[0]), "+f"((c)[1]), "+f"((c)[2]), "+f"((c)[3])             \
        : "r"((a)[0]), "r"((a)[1]), "r"((a)[2]), "r"((a)[3]),                \
          "r"((b)[0]), "r"((b)[1]))

#define PADK 36
#define TILE_FLOATS (128 * PADK)                 // one buffer, one operand
#define SMEM_BYTES (2 * TILE_FLOATS * 4 * 2)     // 73728

#define MODE_RELU_ROUND 0   // bias+relu, tf32-round (feeds next GEMM)
#define MODE_RELU_PLAIN 1   // bias+relu, plain fp32 (feeds dot256)
#define MODE_PLAIN68    2   // bias only, Nout=68 guard

// ---------------------------------------------------------------------------
// tf32 mma.sync GEMM: C[M,Nout] = act(A[M,256] . W[Nout,256]^T + bias)
// A, W pre-rounded to tf32. grid = (ceil(Nout/128), M/128), 256 threads.
// ---------------------------------------------------------------------------
__global__ void __launch_bounds__(256, 2)
gemm_tf32(const float* __restrict__ A, const float* __restrict__ W,
          const float* __restrict__ bias, float* __restrict__ C,
          int Nout, int mode)
{
    extern __shared__ __align__(16) float sm[];
    float* smAf = sm;                       // [2][128][PADK]
    float* smBf = sm + 2 * TILE_FLOATS;     // [2][128][PADK]
    const uint32_t smA = smem_u32(smAf);
    const uint32_t smB = smem_u32(smBf);

    const int tid = threadIdx.x;
    const int bm = blockIdx.y * 128;
    const int bn = blockIdx.x * 128;
    const int warp = tid >> 5, lane = tid & 31;
    const int wm = warp & 1, wn = warp >> 1;     // wm: 0..1 (64 rows), wn: 0..3 (32 cols)
    const int lq = lane >> 2, lr = lane & 3;

    float acc[4][4][4];
#pragma unroll
    for (int i = 0; i < 4; i++)
#pragma unroll
        for (int j = 0; j < 4; j++)
#pragma unroll
            for (int q = 0; q < 4; q++) acc[i][j][q] = 0.f;

    const int lrow = tid >> 3;          // 0..31
    const int lseg = (tid & 7) * 4;     // 0,4,...,28

    // per-thread gmem base pointers (rows lrow, lrow+32, lrow+64, lrow+96)
    const float* aG = A + (size_t)(bm + lrow) * 256 + lseg;
    const float* bG = W + (size_t)(bn + lrow) * 256 + lseg;

    // issue a BK=32 tile load (both operands) into buffer `buf`
#define ISSUE_TILE(buf, k0)                                                   \
    do {                                                                      \
        uint32_t dA = smA + ((buf) * TILE_FLOATS + lrow * PADK + lseg) * 4;   \
        uint32_t dB = smB + ((buf) * TILE_FLOATS + lrow * PADK + lseg) * 4;   \
        _Pragma("unroll")                                                     \
        for (int it = 0; it < 4; it++) {                                      \
            CP16(dA + it * 32 * PADK * 4,                                     \
                 __cvta_generic_to_global(aG + (size_t)it * 32 * 256 + (k0)), \
                 16);                                                         \
            int brow = bn + lrow + it * 32;                                   \
            CP16(dB + it * 32 * PADK * 4,                                     \
                 __cvta_generic_to_global(bG + (size_t)it * 32 * 256 + (k0)), \
                 (brow < Nout) ? 16 : 0);                                     \
        }                                                                     \
        CP_COMMIT();                                                          \
    } while (0)

    ISSUE_TILE(0, 0);

    for (int kt = 0; kt < 8; kt++) {
        const int buf = kt & 1;
        if (kt < 7) { ISSUE_TILE(buf ^ 1, (kt + 1) * 32); CP_WAIT(1); }
        else        { CP_WAIT(0); }
        __syncthreads();

        const float* asw = smAf + buf * TILE_FLOATS + (wm * 64 + lq) * PADK;
        const float* bsw = smBf + buf * TILE_FLOATS + (wn * 32 + lq) * PADK;

#pragma unroll
        for (int kk = 0; kk < 4; kk++) {
            const int k = kk * 8 + lr;
            uint32_t a[4][4], b[4][2];
#pragma unroll
            for (int i = 0; i < 4; i++) {
                const float* p = asw + i * 16 * PADK + k;
                a[i][0] = __float_as_uint(p[0]);
                a[i][1] = __float_as_uint(p[8 * PADK]);
                a[i][2] = __float_as_uint(p[4]);
                a[i][3] = __float_as_uint(p[8 * PADK + 4]);
            }
#pragma unroll
            for (int j = 0; j < 4; j++) {
                const float* p = bsw + j * 8 * PADK + k;
                b[j][0] = __float_as_uint(p[0]);
                b[j][1] = __float_as_uint(p[4]);
            }
#pragma unroll
            for (int i = 0; i < 4; i++)
#pragma unroll
                for (int j = 0; j < 4; j++)
                    MMA8(acc[i][j], a[i], b[j]);
        }
        __syncthreads();
    }

    // Epilogue
    const int ldc = Nout;
#pragma unroll
    for (int i = 0; i < 4; i++) {
#pragma unroll
        for (int j = 0; j < 4; j++) {
            int row = bm + wm * 64 + i * 16 + lq;
            int col = bn + wn * 32 + j * 8 + 2 * lr;
            if (mode == MODE_PLAIN68 && col >= 68) continue;
            float b0 = __ldg(bias + col), b1 = __ldg(bias + col + 1);
            float c0 = acc[i][j][0] + b0, c1 = acc[i][j][1] + b1;
            float c2 = acc[i][j][2] + b0, c3 = acc[i][j][3] + b1;
            if (mode != MODE_PLAIN68) {
                c0 = fmaxf(c0, 0.f); c1 = fmaxf(c1, 0.f);
                c2 = fmaxf(c2, 0.f); c3 = fmaxf(c3, 0.f);
            }
            if (mode == MODE_RELU_ROUND) {
                c0 = tf32r(c0); c1 = tf32r(c1);
                c2 = tf32r(c2); c3 = tf32r(c3);
            }
            *(float2*)(C + (size_t)row * ldc + col)       = make_float2(c0, c1);
            *(float2*)(C + (size_t)(row + 8) * ldc + col) = make_float2(c2, c3);
        }
    }
#undef ISSUE_TILE
}

// ---------------------------------------------------------------------------
// fp32 -> tf32-rounded fp32 (element-wise, float4 vectorized)
// ---------------------------------------------------------------------------
__global__ void __launch_bounds__(256)
round_tf32_kernel(const float4* __restrict__ in, float4* __restrict__ out, long n4)
{
    long i = (long)blockIdx.x * blockDim.x + threadIdx.x;
    if (i >= n4) return;
    float4 v = in[i];
    v.x = tf32r(v.x); v.y = tf32r(v.y); v.z = tf32r(v.z); v.w = tf32r(v.w);
    out[i] = v;
}

// ---------------------------------------------------------------------------
// cls logit: warp-per-row dot over 256 (8 warps/block -> grid = M/8)
// ---------------------------------------------------------------------------
__global__ void __launch_bounds__(256)
dot256_kernel(const float* __restrict__ H, const float* __restrict__ w,
              const float* __restrict__ bptr, float* __restrict__ out, int M)
{
    int gwarp = (blockIdx.x * blockDim.x + threadIdx.x) >> 5;
    int lane = threadIdx.x & 31;
    if (gwarp >= M) return;
    const float* h = H + (size_t)gwarp * 256;
    float s = 0.f;
#pragma unroll
    for (int i = 0; i < 8; i++)
        s = fmaf(h[lane + 32 * i], __ldg(&w[lane + 32 * i]), s);
#pragma unroll
    for (int o = 16; o; o >>= 1) s += __shfl_xor_sync(0xffffffffu, s, o);
    if (lane == 0) out[gwarp] = s + __ldg(bptr);
}

// ---------------------------------------------------------------------------
// Head: softmax-17 x4, top4+mean, quality MLP, sigmoid(cls)*q, integral box.
// ---------------------------------------------------------------------------
__global__ void __launch_bounds__(128)
head_kernel(const float* __restrict__ reg, const float* __restrict__ clsl,
            const float* __restrict__ qw1, const float* __restrict__ qb1,
            const float* __restrict__ qw2, const float* __restrict__ qb2,
            float* __restrict__ outCls, float* __restrict__ outBox, int M)
{
    __shared__ float sw1[REGCH * 20];
    __shared__ float sb1[REGCH];
    __shared__ float sw2[REGCH];
    __shared__ float sb2;
    for (int i = threadIdx.x; i < REGCH * 20; i += blockDim.x) sw1[i] = qw1[i];
    for (int i = threadIdx.x; i < REGCH; i += blockDim.x) {
        sb1[i] = qb1[i];
        sw2[i] = qw2[i];
    }
    if (threadIdx.x == 0) sb2 = qb2[0];
    __syncthreads();

    int p = blockIdx.x * blockDim.x + threadIdx.x;
    if (p >= M) return;

    const float* rp = reg + (size_t)p * REGOUT;
    float stat[20], box[4];
#pragma unroll
    for (int s = 0; s < 4; s++) {
        float v[NBINS];
        float mx = -1e30f;
#pragma unroll
        for (int i = 0; i < NBINS; i++) { v[i] = rp[s * NBINS + i]; mx = fmaxf(mx, v[i]); }
        float sum = 0.f;
#pragma unroll
        for (int i = 0; i < NBINS; i++) { v[i] = expf(v[i] - mx); sum += v[i]; }
        float inv = 1.f / sum, integ = 0.f;
#pragma unroll
        for (int i = 0; i < NBINS; i++) { v[i] *= inv; integ += v[i] * (float)i; }
        box[s] = integ * (1.f / 16.f);
        float mean4 = 0.f;
        for (int k = 0; k < 4; k++) {
            float best = -1.f;
            int bi = 0;
#pragma unroll
            for (int i = 0; i < NBINS; i++)
                if (v[i] > best) { best = v[i]; bi = i; }
            stat[s * 5 + k] = best;
            mean4 += best;
            v[bi] = -2.f;
        }
        stat[s * 5 + 4] = mean4 * 0.25f;
    }
    float q = sb2;
    for (int o = 0; o < REGCH; o++) {
        float h = sb1[o];
#pragma unroll
        for (int c = 0; c < 20; c++) h = fmaf(sw1[o * 20 + c], stat[c], h);
        q = fmaf(sw2[o], fmaxf(h, 0.f), q);
    }
    q = 1.f / (1.f + expf(-q));
    float cl = 1.f / (1.f + expf(-clsl[p]));
    outCls[p] = cl * q;
    *(float4*)&outBox[(size_t)p * 4] = make_float4(box[0], box[1], box[2], box[3]);
}

// ---------------------------------------------------------------------------
// Launcher
// ---------------------------------------------------------------------------
extern "C" void kernel_launch(void* const* d_in, const int* in_sizes, int n_in,
                              void* d_out, int out_size)
{
    const float* x   = (const float*)d_in[0];
    const float* cw1 = (const float*)d_in[1];
    const float* cb1 = (const float*)d_in[2];
    const float* cw2 = (const float*)d_in[3];
    const float* cb2 = (const float*)d_in[4];
    const float* cw3 = (const float*)d_in[5];
    const float* cb3 = (const float*)d_in[6];
    const float* rw1 = (const float*)d_in[7];
    const float* rb1 = (const float*)d_in[8];
    const float* rw2 = (const float*)d_in[9];
    const float* rb2 = (const float*)d_in[10];
    const float* rw3 = (const float*)d_in[11];
    const float* rb3 = (const float*)d_in[12];
    const float* qw1 = (const float*)d_in[13];
    const float* qb1 = (const float*)d_in[14];
    const float* qw2 = (const float*)d_in[15];
    const float* qb2 = (const float*)d_in[16];

    float* out = (float*)d_out;
    float* outCls = out;
    float* outBox = out + (size_t)MROWS;
    float* outReg = out + (size_t)MROWS * 5;

    float *xa, *bufA, *bufB, *clsbuf, *wr;
    cudaGetSymbolAddress((void**)&xa, g_xa);
    cudaGetSymbolAddress((void**)&bufA, g_bufA);
    cudaGetSymbolAddress((void**)&bufB, g_bufB);
    cudaGetSymbolAddress((void**)&clsbuf, g_cls);
    cudaGetSymbolAddress((void**)&wr, g_wr);

    float* wr_cw1 = wr;
    float* wr_cw2 = wr + (size_t)256 * 256;
    float* wr_rw1 = wr + (size_t)512 * 256;
    float* wr_rw2 = wr + (size_t)768 * 256;
    float* wr_rw3 = wr + (size_t)1024 * 256;

    cudaFuncSetAttribute(gemm_tf32, cudaFuncAttributeMaxDynamicSharedMemorySize, SMEM_BYTES);

    // Round operands to tf32
    round_tf32_kernel<<<(MROWS * 64 + 255) / 256, 256>>>((const float4*)x, (float4*)xa,
                                                         (long)MROWS * 64);
    round_tf32_kernel<<<64, 256>>>((const float4*)cw1, (float4*)wr_cw1, 16384);
    round_tf32_kernel<<<64, 256>>>((const float4*)cw2, (float4*)wr_cw2, 16384);
    round_tf32_kernel<<<64, 256>>>((const float4*)rw1, (float4*)wr_rw1, 16384);
    round_tf32_kernel<<<64, 256>>>((const float4*)rw2, (float4*)wr_rw2, 16384);
    round_tf32_kernel<<<17, 256>>>((const float4*)rw3, (float4*)wr_rw3, 4352);

    dim3 g256(2, MROWS / 128);
    dim3 g68(1, MROWS / 128);

    // Classification branch
    gemm_tf32<<<g256, 256, SMEM_BYTES>>>(xa,   wr_cw1, cb1, bufA, 256, MODE_RELU_ROUND);
    gemm_tf32<<<g256, 256, SMEM_BYTES>>>(bufA, wr_cw2, cb2, bufB, 256, MODE_RELU_PLAIN);
    dot256_kernel<<<MROWS / 8, 256>>>(bufB, cw3, cb3, clsbuf, MROWS);

    // Regression branch
    gemm_tf32<<<g256, 256, SMEM_BYTES>>>(xa,   wr_rw1, rb1, bufA, 256, MODE_RELU_ROUND);
    gemm_tf32<<<g256, 256, SMEM_BYTES>>>(bufA, wr_rw2, rb2, bufB, 256, MODE_RELU_ROUND);
    gemm_tf32<<<g68,  256, SMEM_BYTES>>>(bufB, wr_rw3, rb3, outReg, 68, MODE_PLAIN68);

    // Fused head
    head_kernel<<<(MROWS + 127) / 128, 128>>>(outReg, clsbuf, qw1, qb1, qw2, qb2,
                                              outCls, outBox, MROWS);
}

// round 5
// speedup vs baseline: 3.6083x; 1.1235x over previous
#include <cuda_runtime.h>
#include <cuda_bf16.h>
#include <math.h>
#include <stdint.h>

// Problem constants
#define NIMG   32
#define HH     96
#define WW     96
#define LPIX   (HH*WW)              // 9216
#define MROWS  (NIMG*LPIX)          // 294912
#define NBINS  17
#define REGOUT (4*NBINS)            // 68
#define REGCH  64

// ---------------------------------------------------------------------------
// Scratch device globals (allocation-guard safe)
// ---------------------------------------------------------------------------
__device__ __align__(16) float g_buf1[(size_t)MROWS * 512];  // L1 out: [cls h1 | reg h1]
__device__ __align__(16) float g_buf2[(size_t)MROWS * 256];  // reg h2
__device__ float g_cls[MROWS];                               // cls dot accumulator
// rounded weights: [cw1(256) | rw1(256) | cw2(256) | rw2(256) | rw3(68)] x 256
__device__ __align__(16) float g_wr[(size_t)(4 * 256 + 68) * 256];
__device__ float g_b512[512];                                // concat(cb1, rb1)

// ---------------------------------------------------------------------------
// helpers
// ---------------------------------------------------------------------------
__device__ __forceinline__ uint32_t smem_u32(const void* p) {
    uint32_t a;
    asm("{ .reg .u64 t; cvta.to.shared.u64 t, %1; cvt.u32.u64 %0, t; }" : "=r"(a) : "l"(p));
    return a;
}
__device__ __forceinline__ float tf32r(float x) {
    uint32_t u;
    asm("cvt.rna.tf32.f32 %0, %1;" : "=r"(u) : "f"(x));
    return __uint_as_float(u);
}
#define CP16(dst, gsrc, nbytes) \
    asm volatile("cp.async.cg.shared.global [%0], [%1], 16, %2;" \
                 :: "r"(dst), "l"(gsrc), "r"(nbytes))
#define CP_COMMIT() asm volatile("cp.async.commit_group;" ::: "memory")
#define CP_WAIT(n)  asm volatile("cp.async.wait_group %0;" :: "n"(n) : "memory")

#define MMA8(c, a, b)                                                        \
    asm volatile("mma.sync.aligned.m16n8k8.row.col.f32.tf32.tf32.f32 "       \
        "{%0,%1,%2,%3}, {%4,%5,%6,%7}, {%8,%9}, {%0,%1,%2,%3};"              \
        : "+f"((c)[0]), "+f"((c)[1]), "+f"((c)[2]), "+f"((c)[3])             \
        : "r"((a)[0]), "r"((a)[1]), "r"((a)[2]), "r"((a)[3]),                \
          "r"((b)[0]), "r"((b)[1]))

#define PADK 36
#define STAGE_FLOATS (128 * PADK)
#define NSTAGE 3
#define SMEM_BYTES (NSTAGE * STAGE_FLOATS * 4 * 2)   // 110592

#define MODE_STD 0   // bias + relu, store C
#define MODE_P68 1   // bias only, store C with col<68 guard
#define MODE_DOT 2   // bias + relu, dot with w3, atomicAdd into dotOut (no C)

// ---------------------------------------------------------------------------
// tf32 mma.sync GEMM: C[M,Nout] = act(A[M,256] . W[Nout,256]^T + bias)
// A raw fp32 (rounded in-register); W pre-rounded tf32.
// grid = (ceil(Nout/128), M/128), 256 threads, 3-stage cp.async pipeline.
// ---------------------------------------------------------------------------
__global__ void __launch_bounds__(256, 2)
gemm_tf32(const float* __restrict__ A, int lda,
          const float* __restrict__ W,
          const float* __restrict__ bias,
          float* __restrict__ C, int ldc, int Nout, int mode,
          const float* __restrict__ w3, float* __restrict__ dotOut)
{
    extern __shared__ __align__(16) float sm[];
    float* smAf = sm;                              // [NSTAGE][128][PADK]
    float* smBf = sm + NSTAGE * STAGE_FLOATS;      // [NSTAGE][128][PADK]
    const uint32_t smA = smem_u32(smAf);
    const uint32_t smB = smem_u32(smBf);

    const int tid = threadIdx.x;
    const int bm = blockIdx.y * 128;
    const int bn = blockIdx.x * 128;
    const int warp = tid >> 5, lane = tid & 31;
    const int wm = warp & 1, wn = warp >> 1;       // wm: 64-row half, wn: 32-col slice
    const int lq = lane >> 2, lr = lane & 3;

    float acc[4][4][4];
#pragma unroll
    for (int i = 0; i < 4; i++)
#pragma unroll
        for (int j = 0; j < 4; j++)
#pragma unroll
            for (int q = 0; q < 4; q++) acc[i][j][q] = 0.f;

    const int lrow = tid >> 3;          // 0..31
    const int lseg = (tid & 7) * 4;     // 0,4,...,28

    const float* aG = A + (size_t)(bm + lrow) * lda + lseg;
    const float* bG = W + (size_t)(bn + lrow) * 256 + lseg;

#define ISSUE_TILE(buf, k0)                                                   \
    do {                                                                      \
        uint32_t dA = smA + ((buf) * STAGE_FLOATS + lrow * PADK + lseg) * 4;  \
        uint32_t dB = smB + ((buf) * STAGE_FLOATS + lrow * PADK + lseg) * 4;  \
        _Pragma("unroll")                                                     \
        for (int it = 0; it < 4; it++) {                                      \
            CP16(dA + it * 32 * PADK * 4,                                     \
                 __cvta_generic_to_global(aG + (size_t)it * 32 * lda + (k0)), \
                 16);                                                         \
            int brow = bn + lrow + it * 32;                                   \
            CP16(dB + it * 32 * PADK * 4,                                     \
                 __cvta_generic_to_global(bG + (size_t)it * 32 * 256 + (k0)), \
                 (brow < Nout) ? 16 : 0);                                     \
        }                                                                     \
        CP_COMMIT();                                                          \
    } while (0)

    ISSUE_TILE(0, 0);
    ISSUE_TILE(1, 32);

    for (int kt = 0; kt < 8; kt++) {
        if (kt < 6) ISSUE_TILE((kt + 2) % NSTAGE, (kt + 2) * 32);
        else        CP_COMMIT();   // empty group keeps wait-count semantics
        CP_WAIT(2);
        __syncthreads();

        const int buf = kt % NSTAGE;
        const float* asw = smAf + buf * STAGE_FLOATS + (wm * 64 + lq) * PADK;
        const float* bsw = smBf + buf * STAGE_FLOATS + (wn * 32 + lq) * PADK;

#pragma unroll
        for (int kk = 0; kk < 4; kk++) {
            const int k = kk * 8 + lr;
            uint32_t a[4][4], b[4][2];
#pragma unroll
            for (int i = 0; i < 4; i++) {
                const float* p = asw + i * 16 * PADK + k;
                a[i][0] = __float_as_uint(tf32r(p[0]));
                a[i][1] = __float_as_uint(tf32r(p[8 * PADK]));
                a[i][2] = __float_as_uint(tf32r(p[4]));
                a[i][3] = __float_as_uint(tf32r(p[8 * PADK + 4]));
            }
#pragma unroll
            for (int j = 0; j < 4; j++) {
                const float* p = bsw + j * 8 * PADK + k;
                b[j][0] = __float_as_uint(p[0]);
                b[j][1] = __float_as_uint(p[4]);
            }
#pragma unroll
            for (int i = 0; i < 4; i++)
#pragma unroll
                for (int j = 0; j < 4; j++)
                    MMA8(acc[i][j], a[i], b[j]);
        }
        __syncthreads();
    }
#undef ISSUE_TILE

    // ---------------- Epilogue ----------------
    if (mode == MODE_DOT) {
#pragma unroll
        for (int i = 0; i < 4; i++) {
            int r0 = bm + wm * 64 + i * 16 + lq;
            float s0 = 0.f, s1 = 0.f;
#pragma unroll
            for (int j = 0; j < 4; j++) {
                int col = bn + wn * 32 + j * 8 + 2 * lr;
                float b0 = __ldg(bias + col), b1 = __ldg(bias + col + 1);
                float w0 = __ldg(w3 + col), w1 = __ldg(w3 + col + 1);
                float c0 = fmaxf(acc[i][j][0] + b0, 0.f);
                float c1 = fmaxf(acc[i][j][1] + b1, 0.f);
                float c2 = fmaxf(acc[i][j][2] + b0, 0.f);
                float c3 = fmaxf(acc[i][j][3] + b1, 0.f);
                s0 = fmaf(c0, w0, fmaf(c1, w1, s0));
                s1 = fmaf(c2, w0, fmaf(c3, w1, s1));
            }
#pragma unroll
            for (int o = 1; o < 4; o <<= 1) {
                s0 += __shfl_xor_sync(0xffffffffu, s0, o);
                s1 += __shfl_xor_sync(0xffffffffu, s1, o);
            }
            if (lr == 0) {
                atomicAdd(dotOut + r0, s0);
                atomicAdd(dotOut + r0 + 8, s1);
            }
        }
        return;
    }

#pragma unroll
    for (int i = 0; i < 4; i++) {
#pragma unroll
        for (int j = 0; j < 4; j++) {
            int row = bm + wm * 64 + i * 16 + lq;
            int col = bn + wn * 32 + j * 8 + 2 * lr;
            if (mode == MODE_P68 && col >= 68) continue;
            float b0 = __ldg(bias + col), b1 = __ldg(bias + col + 1);
            float c0 = acc[i][j][0] + b0, c1 = acc[i][j][1] + b1;
            float c2 = acc[i][j][2] + b0, c3 = acc[i][j][3] + b1;
            if (mode == MODE_STD) {
                c0 = fmaxf(c0, 0.f); c1 = fmaxf(c1, 0.f);
                c2 = fmaxf(c2, 0.f); c3 = fmaxf(c3, 0.f);
            }
            *(float2*)(C + (size_t)row * ldc + col)       = make_float2(c0, c1);
            *(float2*)(C + (size_t)(row + 8) * ldc + col) = make_float2(c2, c3);
        }
    }
}

// ---------------------------------------------------------------------------
// fp32 -> tf32-rounded fp32 (weights only; tiny)
// ---------------------------------------------------------------------------
__global__ void __launch_bounds__(256)
round_tf32_kernel(const float4* __restrict__ in, float4* __restrict__ out, long n4)
{
    long i = (long)blockIdx.x * blockDim.x + threadIdx.x;
    if (i >= n4) return;
    float4 v = in[i];
    v.x = tf32r(v.x); v.y = tf32r(v.y); v.z = tf32r(v.z); v.w = tf32r(v.w);
    out[i] = v;
}

__global__ void __launch_bounds__(256)
zero_kernel(float* __restrict__ p, int n)
{
    int i = blockIdx.x * blockDim.x + threadIdx.x;
    if (i < n) p[i] = 0.f;
}

// ---------------------------------------------------------------------------
// Head: softmax-17 x4, top4+mean, quality MLP, sigmoid(cls)*q, integral box.
// ---------------------------------------------------------------------------
__global__ void __launch_bounds__(128)
head_kernel(const float* __restrict__ reg, const float* __restrict__ clsl,
            const float* __restrict__ cb3,
            const float* __restrict__ qw1, const float* __restrict__ qb1,
            const float* __restrict__ qw2, const float* __restrict__ qb2,
            float* __restrict__ outCls, float* __restrict__ outBox, int M)
{
    __shared__ float sw1[REGCH * 20];
    __shared__ float sb1[REGCH];
    __shared__ float sw2[REGCH];
    __shared__ float sb2;
    for (int i = threadIdx.x; i < REGCH * 20; i += blockDim.x) sw1[i] = qw1[i];
    for (int i = threadIdx.x; i < REGCH; i += blockDim.x) {
        sb1[i] = qb1[i];
        sw2[i] = qw2[i];
    }
    if (threadIdx.x == 0) sb2 = qb2[0];
    __syncthreads();

    int p = blockIdx.x * blockDim.x + threadIdx.x;
    if (p >= M) return;

    const float* rp = reg + (size_t)p * REGOUT;
    float stat[20], box[4];
#pragma unroll
    for (int s = 0; s < 4; s++) {
        float v[NBINS];
        float mx = -1e30f;
#pragma unroll
        for (int i = 0; i < NBINS; i++) { v[i] = rp[s * NBINS + i]; mx = fmaxf(mx, v[i]); }
        float sum = 0.f;
#pragma unroll
        for (int i = 0; i < NBINS; i++) { v[i] = expf(v[i] - mx); sum += v[i]; }
        float inv = 1.f / sum, integ = 0.f;
#pragma unroll
        for (int i = 0; i < NBINS; i++) { v[i] *= inv; integ += v[i] * (float)i; }
        box[s] = integ * (1.f / 16.f);
        float mean4 = 0.f;
        for (int k = 0; k < 4; k++) {
            float best = -1.f;
            int bi = 0;
#pragma unroll
            for (int i = 0; i < NBINS; i++)
                if (v[i] > best) { best = v[i]; bi = i; }
            stat[s * 5 + k] = best;
            mean4 += best;
            v[bi] = -2.f;
        }
        stat[s * 5 + 4] = mean4 * 0.25f;
    }
    float q = sb2;
    for (int o = 0; o < REGCH; o++) {
        float h = sb1[o];
#pragma unroll
        for (int c = 0; c < 20; c++) h = fmaf(sw1[o * 20 + c], stat[c], h);
        q = fmaf(sw2[o], fmaxf(h, 0.f), q);
    }
    q = 1.f / (1.f + expf(-q));
    float cl = 1.f / (1.f + expf(-(clsl[p] + __ldg(cb3))));
    outCls[p] = cl * q;
    *(float4*)&outBox[(size_t)p * 4] = make_float4(box[0], box[1], box[2], box[3]);
}

// ---------------------------------------------------------------------------
// Launcher
// ---------------------------------------------------------------------------
extern "C" void kernel_launch(void* const* d_in, const int* in_sizes, int n_in,
                              void* d_out, int out_size)
{
    const float* x   = (const float*)d_in[0];
    const float* cw1 = (const float*)d_in[1];
    const float* cb1 = (const float*)d_in[2];
    const float* cw2 = (const float*)d_in[3];
    const float* cb2 = (const float*)d_in[4];
    const float* cw3 = (const float*)d_in[5];
    const float* cb3 = (const float*)d_in[6];
    const float* rw1 = (const float*)d_in[7];
    const float* rb1 = (const float*)d_in[8];
    const float* rw2 = (const float*)d_in[9];
    const float* rb2 = (const float*)d_in[10];
    const float* rw3 = (const float*)d_in[11];
    const float* rb3 = (const float*)d_in[12];
    const float* qw1 = (const float*)d_in[13];
    const float* qb1 = (const float*)d_in[14];
    const float* qw2 = (const float*)d_in[15];
    const float* qb2 = (const float*)d_in[16];

    float* out = (float*)d_out;
    float* outCls = out;
    float* outBox = out + (size_t)MROWS;
    float* outReg = out + (size_t)MROWS * 5;

    float *buf1, *buf2, *clsbuf, *wr, *b512;
    cudaGetSymbolAddress((void**)&buf1, g_buf1);
    cudaGetSymbolAddress((void**)&buf2, g_buf2);
    cudaGetSymbolAddress((void**)&clsbuf, g_cls);
    cudaGetSymbolAddress((void**)&wr, g_wr);
    cudaGetSymbolAddress((void**)&b512, g_b512);

    float* wr_l1  = wr;                          // cw1 rows 0..255, rw1 rows 256..511
    float* wr_cw2 = wr + (size_t)512 * 256;
    float* wr_rw2 = wr + (size_t)768 * 256;
    float* wr_rw3 = wr + (size_t)1024 * 256;

    cudaFuncSetAttribute(gemm_tf32, cudaFuncAttributeMaxDynamicSharedMemorySize, SMEM_BYTES);

    // Round weights to tf32; concat L1 weights/biases
    round_tf32_kernel<<<64, 256>>>((const float4*)cw1, (float4*)wr_l1, 16384);
    round_tf32_kernel<<<64, 256>>>((const float4*)rw1, (float4*)(wr_l1 + (size_t)256 * 256), 16384);
    round_tf32_kernel<<<64, 256>>>((const float4*)cw2, (float4*)wr_cw2, 16384);
    round_tf32_kernel<<<64, 256>>>((const float4*)rw2, (float4*)wr_rw2, 16384);
    round_tf32_kernel<<<17, 256>>>((const float4*)rw3, (float4*)wr_rw3, 4352);
    cudaMemcpyAsync(b512,       cb1, 256 * sizeof(float), cudaMemcpyDeviceToDevice);
    cudaMemcpyAsync(b512 + 256, rb1, 256 * sizeof(float), cudaMemcpyDeviceToDevice);
    zero_kernel<<<MROWS / 256, 256>>>(clsbuf, MROWS);

    const int GY = MROWS / 128;  // 2304

    // Fused layer-1: x -> [cls h1 | reg h1]  (reads x once)
    gemm_tf32<<<dim3(4, GY), 256, SMEM_BYTES>>>(x, 256, wr_l1, b512,
                                                buf1, 512, 512, MODE_STD, nullptr, nullptr);
    // cls layer-2 + fused dot with cw3 -> clsbuf
    gemm_tf32<<<dim3(2, GY), 256, SMEM_BYTES>>>(buf1, 512, wr_cw2, cb2,
                                                nullptr, 0, 256, MODE_DOT, cw3, clsbuf);
    // reg layer-2
    gemm_tf32<<<dim3(2, GY), 256, SMEM_BYTES>>>(buf1 + 256, 512, wr_rw2, rb2,
                                                buf2, 256, 256, MODE_STD, nullptr, nullptr);
    // reg layer-3 (68 outputs) -> reg_pred output
    gemm_tf32<<<dim3(1, GY), 256, SMEM_BYTES>>>(buf2, 256, wr_rw3, rb3,
                                                outReg, 68, 68, MODE_P68, nullptr, nullptr);
    // Fused head
    head_kernel<<<(MROWS + 127) / 128, 128>>>(outReg, clsbuf, cb3, qw1, qb1, qw2, qb2,
                                              outCls, outBox, MROWS);
}